// round 11
// baseline (speedup 1.0000x reference)
#include <cuda_runtime.h>
#include <cstdint>

#define N_SAMPLES 16384
#define DIM       1024
#define ROW_BYTES (DIM * 4)              // 4096 B per row
#define CHUNKS    (DIM / 4 / 32)         // 8 float4 per lane per row
#define MARGIN    1.0f
#define EPSF      1e-6f
#define BLOCK     256
#define WARPS     8                      // warp-per-sample
#define GRID      (N_SAMPLES / WARPS)    // 2048 blocks
#define SMEM_DATA (WARPS * 3 * ROW_BYTES)  // 96 KB row staging
#define SMEM_TOTAL (SMEM_DATA + 64)        // + mbarriers

__device__ double g_acc;      // zero at load; reset by last block each call
__device__ unsigned g_count;

__device__ __forceinline__ uint32_t smem_u32(const void* p) {
    uint32_t a;
    asm("{ .reg .u64 t; cvta.to.shared.u64 t, %1; cvt.u32.u64 %0, t; }"
        : "=r"(a) : "l"(p));
    return a;
}

__device__ __forceinline__ void bulk_g2s(uint32_t dst, const void* src,
                                         uint32_t bytes, uint32_t mbar) {
    asm volatile(
        "cp.async.bulk.shared::cta.global.mbarrier::complete_tx::bytes "
        "[%0], [%1], %2, [%3];"
        :: "r"(dst), "l"(src), "r"(bytes), "r"(mbar) : "memory");
}

__device__ __forceinline__ void mbar_wait(uint32_t mbar, uint32_t parity) {
    asm volatile(
        "{\n\t"
        ".reg .pred P;\n\t"
        "W_%=:\n\t"
        "mbarrier.try_wait.parity.acquire.cta.shared::cta.b64 P, [%0], %1, 0x989680;\n\t"
        "@P bra.uni D_%=;\n\t"
        "bra.uni W_%=;\n\t"
        "D_%=:\n\t"
        "}"
        :: "r"(mbar), "r"(parity) : "memory");
}

__device__ __forceinline__ float dot4(float4 u, float4 v) {
    return u.x*v.x + u.y*v.y + u.z*v.z + u.w*v.w;
}

__global__ __launch_bounds__(BLOCK)
void cl_bulk_kernel(const float* __restrict__ emb,
                    const int* __restrict__ pos_idx,
                    const int* __restrict__ neg_idx,
                    float* __restrict__ out)
{
    extern __shared__ char smem[];
    const int wid  = threadIdx.x >> 5;
    const int lane = threadIdx.x & 31;
    const int i    = blockIdx.x * WARPS + wid;   // sample for this warp

    char* my = smem + wid * 3 * ROW_BYTES;       // this warp's 12KB slot
    const uint32_t mbar_base = smem_u32(smem + SMEM_DATA);
    const uint32_t mbar = mbar_base + wid * 8;

    if (threadIdx.x < WARPS) {
        asm volatile("mbarrier.init.shared.b64 [%0], %1;"
                     :: "r"(mbar_base + threadIdx.x * 8), "r"(1) : "memory");
    }
    __syncthreads();

    // Lane 0: stage all three rows with bulk async copies (bypass L1tex path).
    if (lane == 0) {
        const int p = pos_idx[i];
        const int n = neg_idx[i];
        asm volatile("mbarrier.arrive.expect_tx.shared.b64 _, [%0], %1;"
                     :: "r"(mbar), "r"(3 * ROW_BYTES) : "memory");
        const uint32_t d = smem_u32(my);
        bulk_g2s(d,                 emb + (size_t)i * DIM, ROW_BYTES, mbar);
        bulk_g2s(d + ROW_BYTES,     emb + (size_t)p * DIM, ROW_BYTES, mbar);
        bulk_g2s(d + 2 * ROW_BYTES, emb + (size_t)n * DIM, ROW_BYTES, mbar);
    }
    mbar_wait(mbar, 0);   // single phase per launch (fresh smem every replay)

    // Consume from SMEM: conflict-free LDS.128 streams.
    const float4* A = (const float4*)(my);
    const float4* B = (const float4*)(my + ROW_BYTES);
    const float4* C = (const float4*)(my + 2 * ROW_BYTES);

    float sa = 0.f, sb = 0.f, sc = 0.f, dab = 0.f, dac = 0.f;
    #pragma unroll
    for (int c = 0; c < CHUNKS; c++) {
        const int idx = c * 32 + lane;
        float4 a = A[idx];
        float4 b = B[idx];
        float4 cc = C[idx];
        sa  += dot4(a, a);
        sb  += dot4(b, b);
        sc  += dot4(cc, cc);
        dab += dot4(a, b);
        dac += dot4(a, cc);
    }

    #pragma unroll
    for (int o = 16; o > 0; o >>= 1) {
        sa  += __shfl_xor_sync(0xffffffffu, sa,  o);
        sb  += __shfl_xor_sync(0xffffffffu, sb,  o);
        sc  += __shfl_xor_sync(0xffffffffu, sc,  o);
        dab += __shfl_xor_sync(0xffffffffu, dab, o);
        dac += __shfl_xor_sync(0xffffffffu, dac, o);
    }

    __shared__ double warp_loss[WARPS];
    if (lane == 0) {
        // F.normalize: 1/max(||x||, eps)
        const float ia = 1.0f / fmaxf(sqrtf(sa), EPSF);
        const float ib = 1.0f / fmaxf(sqrtf(sb), EPSF);
        const float ic = 1.0f / fmaxf(sqrtf(sc), EPSF);

        // ||u - v + eps||^2 expanded (mean-zero eps cross-term dropped)
        const float de2 = (float)DIM * EPSF * EPSF;
        float dp = fmaxf(sa*ia*ia + sb*ib*ib - 2.0f*dab*ia*ib + de2, 0.0f);
        float dn = fmaxf(sa*ia*ia + sc*ic*ic - 2.0f*dac*ia*ic + de2, 0.0f);

        const float d_pos = sqrtf(dp) + EPSF;    // pairwise_distance + module eps
        const float d_neg = sqrtf(dn) + EPSF;

        const float tn = fmaxf(MARGIN - d_neg, EPSF);
        warp_loss[wid] = (double)(d_pos * d_pos + tn * tn);
    }
    __syncthreads();

    if (threadIdx.x == 0) {
        double blk = 0.0;
        #pragma unroll
        for (int w = 0; w < WARPS; w++) blk += warp_loss[w];

        atomicAdd(&g_acc, blk);
        __threadfence();
        unsigned done = atomicAdd(&g_count, 1u);
        if (done == GRID - 1u) {
            out[0] = (float)(g_acc / (2.0 * (double)N_SAMPLES));
            g_acc = 0.0;      // reset for next graph replay
            g_count = 0u;
            __threadfence();
        }
    }
}

extern "C" void kernel_launch(void* const* d_in, const int* in_sizes, int n_in,
                              void* d_out, int out_size)
{
    const float* emb = (const float*)d_in[0];
    // d_in[1] = labels (int32) — unused by the loss
    const int*   pos = (const int*)d_in[2];
    const int*   neg = (const int*)d_in[3];
    float* out = (float*)d_out;

    cudaFuncSetAttribute(cl_bulk_kernel,
                         cudaFuncAttributeMaxDynamicSharedMemorySize, SMEM_TOTAL);
    cl_bulk_kernel<<<GRID, BLOCK, SMEM_TOTAL>>>(emb, pos, neg, out);
}

// round 12
// speedup vs baseline: 1.1220x; 1.1220x over previous
#include <cuda_runtime.h>
#include <cstdint>

#define N_SAMPLES 16384
#define DIM       1024
#define ROW_BYTES (DIM * 4)             // 4096 B
#define CHUNKS    8                     // float4-chunks per lane per row
#define MARGIN    1.0f
#define EPSF      1e-6f
#define BLOCK     256
#define WARPS     8
#define SPW       16                    // samples per warp (pipelined)
#define GRID      (N_SAMPLES / (WARPS * SPW))   // 128 blocks (1 CTA/SM)
#define BUF_BYTES (3 * ROW_BYTES)       // 12 KB per sample
#define SMEM_TOTAL (WARPS * 2 * BUF_BYTES)      // 192 KB double-buffered

__device__ double g_acc;      // zero at load; reset by last block each call
__device__ unsigned g_count;

__device__ __forceinline__ uint32_t smem_u32(const void* p) {
    uint32_t a;
    asm("{ .reg .u64 t; cvta.to.shared.u64 t, %1; cvt.u32.u64 %0, t; }"
        : "=r"(a) : "l"(p));
    return a;
}

__device__ __forceinline__ void cpa16(uint32_t dst, const void* src) {
    asm volatile("cp.async.cg.shared.global [%0], [%1], 16;"
                 :: "r"(dst), "l"(src) : "memory");
}
__device__ __forceinline__ void cpa_commit() {
    asm volatile("cp.async.commit_group;" ::: "memory");
}
__device__ __forceinline__ void cpa_wait1() {
    asm volatile("cp.async.wait_group 1;" ::: "memory");
}

__device__ __forceinline__ float dot4(float4 u, float4 v) {
    return u.x*v.x + u.y*v.y + u.z*v.z + u.w*v.w;
}

__global__ __launch_bounds__(BLOCK)
void cl_pipe_kernel(const float* __restrict__ emb,
                    const int* __restrict__ pos_idx,
                    const int* __restrict__ neg_idx,
                    float* __restrict__ out)
{
    extern __shared__ char smem[];
    const int wid  = threadIdx.x >> 5;
    const int lane = threadIdx.x & 31;
    const int base = (blockIdx.x * WARPS + wid) * SPW;   // first sample of warp

    char* slot = smem + wid * 2 * BUF_BYTES;
    const uint32_t s0 = smem_u32(slot);
    const uint32_t s1 = s0 + BUF_BYTES;

    // stage(sample, buf): each thread copies exactly the float4s it will read.
    auto stage = [&](int s, uint32_t buf) {
        const int i = base + s;
        const int p = pos_idx[i];
        const int n = neg_idx[i];
        const float* ra = emb + (size_t)i * DIM;
        const float* rb = emb + (size_t)p * DIM;
        const float* rc = emb + (size_t)n * DIM;
        #pragma unroll
        for (int c = 0; c < CHUNKS; c++) {
            const uint32_t off = (uint32_t)(c * 32 + lane) * 16u;
            cpa16(buf + off,                 ra + (c * 32 + lane) * 4);
            cpa16(buf + ROW_BYTES + off,     rb + (c * 32 + lane) * 4);
            cpa16(buf + 2 * ROW_BYTES + off, rc + (c * 32 + lane) * 4);
        }
    };

    stage(0, s0);
    cpa_commit();

    double acc = 0.0;   // meaningful on lane 0

    for (int s = 0; s < SPW; s++) {
        if (s + 1 < SPW) stage(s + 1, (s & 1) ? s0 : s1);
        cpa_commit();          // (possibly empty group on last iter)
        cpa_wait1();           // sample s's group complete

        const uint32_t buf = (s & 1) ? s1 : s0;
        const float4* A = (const float4*)(slot + (buf - s0));
        const float4* B = (const float4*)((const char*)A + ROW_BYTES);
        const float4* C = (const float4*)((const char*)A + 2 * ROW_BYTES);

        float sa = 0.f, sb = 0.f, sc = 0.f, dab = 0.f, dac = 0.f;
        #pragma unroll
        for (int c = 0; c < CHUNKS; c++) {
            const int idx = c * 32 + lane;     // exactly what this thread staged
            float4 a = A[idx];
            float4 b = B[idx];
            float4 cc = C[idx];
            sa  += dot4(a, a);
            sb  += dot4(b, b);
            sc  += dot4(cc, cc);
            dab += dot4(a, b);
            dac += dot4(a, cc);
        }

        #pragma unroll
        for (int o = 16; o > 0; o >>= 1) {
            sa  += __shfl_xor_sync(0xffffffffu, sa,  o);
            sb  += __shfl_xor_sync(0xffffffffu, sb,  o);
            sc  += __shfl_xor_sync(0xffffffffu, sc,  o);
            dab += __shfl_xor_sync(0xffffffffu, dab, o);
            dac += __shfl_xor_sync(0xffffffffu, dac, o);
        }

        if (lane == 0) {
            const float ia = 1.0f / fmaxf(sqrtf(sa), EPSF);
            const float ib = 1.0f / fmaxf(sqrtf(sb), EPSF);
            const float ic = 1.0f / fmaxf(sqrtf(sc), EPSF);
            const float de2 = (float)DIM * EPSF * EPSF;
            float dp = fmaxf(sa*ia*ia + sb*ib*ib - 2.0f*dab*ia*ib + de2, 0.0f);
            float dn = fmaxf(sa*ia*ia + sc*ic*ic - 2.0f*dac*ia*ic + de2, 0.0f);
            const float d_pos = sqrtf(dp) + EPSF;
            const float d_neg = sqrtf(dn) + EPSF;
            const float tn = fmaxf(MARGIN - d_neg, EPSF);
            acc += (double)(d_pos * d_pos + tn * tn);
        }
    }

    __shared__ double warp_loss[WARPS];
    if (lane == 0) warp_loss[wid] = acc;
    __syncthreads();

    if (threadIdx.x == 0) {
        double blk = 0.0;
        #pragma unroll
        for (int w = 0; w < WARPS; w++) blk += warp_loss[w];

        atomicAdd(&g_acc, blk);
        __threadfence();
        unsigned done = atomicAdd(&g_count, 1u);
        if (done == GRID - 1u) {
            out[0] = (float)(g_acc / (2.0 * (double)N_SAMPLES));
            g_acc = 0.0;      // reset for next graph replay
            g_count = 0u;
            __threadfence();
        }
    }
}

extern "C" void kernel_launch(void* const* d_in, const int* in_sizes, int n_in,
                              void* d_out, int out_size)
{
    const float* emb = (const float*)d_in[0];
    // d_in[1] = labels (int32) — unused by the loss
    const int*   pos = (const int*)d_in[2];
    const int*   neg = (const int*)d_in[3];
    float* out = (float*)d_out;

    cudaFuncSetAttribute(cl_pipe_kernel,
                         cudaFuncAttributeMaxDynamicSharedMemorySize, SMEM_TOTAL);
    cl_pipe_kernel<<<GRID, BLOCK, SMEM_TOTAL>>>(emb, pos, neg, out);
}

// round 13
// speedup vs baseline: 1.5165x; 1.3516x over previous
#include <cuda_runtime.h>

#define N_SAMPLES 16384
#define DIM       1024
#define CHUNKS    (DIM / 4 / 32)        // 8 float4-chunks per lane per row
#define MARGIN    1.0f
#define EPSF      1e-6f
#define BLOCK     256
#define WARPS     (BLOCK / 32)          // 8 warps
#define SPW       2                     // samples per warp
#define SPB       (WARPS * SPW)         // 16 samples per block
#define GRID      (N_SAMPLES / SPB)     // 1024 blocks

__device__ double g_acc;      // zero at load; reset by last block each call
__device__ unsigned g_count;

__device__ __forceinline__ float dot4(float4 u, float4 v) {
    return u.x*v.x + u.y*v.y + u.z*v.z + u.w*v.w;
}

// L2-only load (no L1 allocation — zero reuse gather, skip the L1 overhead)
__device__ __forceinline__ float4 ldcg4(const float4* p) {
    return __ldcg(p);
}

__global__ __launch_bounds__(BLOCK)
void cl_dot2cg_kernel(const float* __restrict__ emb,
                      const int* __restrict__ pos_idx,
                      const int* __restrict__ neg_idx,
                      float* __restrict__ out)
{
    const int wid  = threadIdx.x >> 5;
    const int lane = threadIdx.x & 31;
    const int i0 = blockIdx.x * SPB + wid * SPW;
    const int i1 = i0 + 1;

    const int p0 = __ldg(pos_idx + i0), n0 = __ldg(neg_idx + i0);
    const int p1 = __ldg(pos_idx + i1), n1 = __ldg(neg_idx + i1);

    const float4* ra0 = (const float4*)(emb + (size_t)i0 * DIM);
    const float4* rb0 = (const float4*)(emb + (size_t)p0 * DIM);
    const float4* rc0 = (const float4*)(emb + (size_t)n0 * DIM);
    const float4* ra1 = (const float4*)(emb + (size_t)i1 * DIM);
    const float4* rb1 = (const float4*)(emb + (size_t)p1 * DIM);
    const float4* rc1 = (const float4*)(emb + (size_t)n1 * DIM);

    float sa0 = 0.f, sb0 = 0.f, sc0 = 0.f, dab0 = 0.f, dac0 = 0.f;
    float sa1 = 0.f, sb1 = 0.f, sc1 = 0.f, dab1 = 0.f, dac1 = 0.f;

    #pragma unroll
    for (int c = 0; c < CHUNKS; c++) {
        const int idx = c * 32 + lane;           // coalesced 512B per chunk-load
        float4 a0 = ldcg4(ra0 + idx);
        float4 b0 = ldcg4(rb0 + idx);
        float4 c0 = ldcg4(rc0 + idx);
        float4 a1 = ldcg4(ra1 + idx);
        float4 b1 = ldcg4(rb1 + idx);
        float4 c1 = ldcg4(rc1 + idx);

        sa0  += dot4(a0, a0);
        sb0  += dot4(b0, b0);
        sc0  += dot4(c0, c0);
        dab0 += dot4(a0, b0);
        dac0 += dot4(a0, c0);

        sa1  += dot4(a1, a1);
        sb1  += dot4(b1, b1);
        sc1  += dot4(c1, c1);
        dab1 += dot4(a1, b1);
        dac1 += dot4(a1, c1);
    }

    #pragma unroll
    for (int o = 16; o > 0; o >>= 1) {
        sa0  += __shfl_xor_sync(0xffffffffu, sa0,  o);
        sb0  += __shfl_xor_sync(0xffffffffu, sb0,  o);
        sc0  += __shfl_xor_sync(0xffffffffu, sc0,  o);
        dab0 += __shfl_xor_sync(0xffffffffu, dab0, o);
        dac0 += __shfl_xor_sync(0xffffffffu, dac0, o);
        sa1  += __shfl_xor_sync(0xffffffffu, sa1,  o);
        sb1  += __shfl_xor_sync(0xffffffffu, sb1,  o);
        sc1  += __shfl_xor_sync(0xffffffffu, sc1,  o);
        dab1 += __shfl_xor_sync(0xffffffffu, dab1, o);
        dac1 += __shfl_xor_sync(0xffffffffu, dac1, o);
    }

    __shared__ double warp_loss[WARPS];
    if (lane == 0) {
        const float de2 = (float)DIM * EPSF * EPSF;

        // sample 0
        float ia = 1.0f / fmaxf(sqrtf(sa0), EPSF);
        float ib = 1.0f / fmaxf(sqrtf(sb0), EPSF);
        float ic = 1.0f / fmaxf(sqrtf(sc0), EPSF);
        float dp = fmaxf(sa0*ia*ia + sb0*ib*ib - 2.0f*dab0*ia*ib + de2, 0.0f);
        float dn = fmaxf(sa0*ia*ia + sc0*ic*ic - 2.0f*dac0*ia*ic + de2, 0.0f);
        float d_pos = sqrtf(dp) + EPSF;
        float d_neg = sqrtf(dn) + EPSF;
        float tn = fmaxf(MARGIN - d_neg, EPSF);
        double acc = (double)(d_pos * d_pos + tn * tn);

        // sample 1
        ia = 1.0f / fmaxf(sqrtf(sa1), EPSF);
        ib = 1.0f / fmaxf(sqrtf(sb1), EPSF);
        ic = 1.0f / fmaxf(sqrtf(sc1), EPSF);
        dp = fmaxf(sa1*ia*ia + sb1*ib*ib - 2.0f*dab1*ia*ib + de2, 0.0f);
        dn = fmaxf(sa1*ia*ia + sc1*ic*ic - 2.0f*dac1*ia*ic + de2, 0.0f);
        d_pos = sqrtf(dp) + EPSF;
        d_neg = sqrtf(dn) + EPSF;
        tn = fmaxf(MARGIN - d_neg, EPSF);
        acc += (double)(d_pos * d_pos + tn * tn);

        warp_loss[wid] = acc;
    }
    __syncthreads();

    if (threadIdx.x == 0) {
        double blk = 0.0;
        #pragma unroll
        for (int w = 0; w < WARPS; w++) blk += warp_loss[w];

        atomicAdd(&g_acc, blk);
        __threadfence();
        unsigned done = atomicAdd(&g_count, 1u);
        if (done == GRID - 1u) {
            out[0] = (float)(g_acc / (2.0 * (double)N_SAMPLES));
            g_acc = 0.0;      // reset for next graph replay
            g_count = 0u;
            __threadfence();
        }
    }
}

extern "C" void kernel_launch(void* const* d_in, const int* in_sizes, int n_in,
                              void* d_out, int out_size)
{
    const float* emb = (const float*)d_in[0];
    // d_in[1] = labels (int32) — unused by the loss
    const int*   pos = (const int*)d_in[2];
    const int*   neg = (const int*)d_in[3];
    float* out = (float*)d_out;

    cl_dot2cg_kernel<<<GRID, BLOCK>>>(emb, pos, neg, out);
}